// round 6
// baseline (speedup 1.0000x reference)
#include <cuda_runtime.h>
#include <cuda_bf16.h>
#include <cstdint>
#include <math.h>

#define B_DIM 1024
#define H_DIM 1024
#define K2B   2048           // int8 bytes per row: [X1(1024) | X2(1024)]
#define V_OUT 50000
#define V_INP 32000
#define SRC   256
#define NPAD  50176          // 392 * 128
#define BMi   128
#define BNi   128
#define NG    8              // k-groups of 128 int8
#define STAGES 3
#define STG   65536          // X1 16K | X2 16K | Y1 16K | Y2 16K
#define X1OFF 0
#define X2OFF 16384
#define Y1OFF 32768
#define Y2OFF 49152
#define GTHR  256

// ---------------- scratch (device globals; no runtime alloc) ----------------
__device__ float  g_scores[(size_t)B_DIM * V_OUT];
__device__ int8_t g_xa8[(size_t)B_DIM * K2B];
__device__ int8_t g_wb8[(size_t)NPAD * K2B];
__device__ float  g_sxa[B_DIM];
__device__ float  g_swb[NPAD];
__device__ float  g_biasg[NPAD];
__device__ int    g_winner[V_OUT];
__device__ int    g_dest[V_INP];

// ---------------- PTX helpers -----------------------------------------------
__device__ __forceinline__ uint32_t smem_u32(const void* p) {
    uint32_t a;
    asm("{ .reg .u64 t; cvta.to.shared.u64 t, %1; cvt.u32.u64 %0, t; }" : "=r"(a) : "l"(p));
    return a;
}
#define CP16(dst, src)  asm volatile("cp.async.cg.shared.global [%0], [%1], 16;" :: "r"(dst), "l"(src))
#define CP_COMMIT()     asm volatile("cp.async.commit_group;" ::: "memory")
#define CP_WAIT(n)      asm volatile("cp.async.wait_group %0;" :: "n"(n) : "memory")
#define SWZ(b) ((b) ^ (((b) >> 3) & 0x70))

__device__ __forceinline__ void ldsm_x4(uint32_t* r, uint32_t addr) {
    asm volatile("ldmatrix.sync.aligned.m8n8.x4.shared.b16 {%0,%1,%2,%3}, [%4];"
                 : "=r"(r[0]), "=r"(r[1]), "=r"(r[2]), "=r"(r[3]) : "r"(addr));
}
__device__ __forceinline__ void ldsm_x2(uint32_t* r, uint32_t addr) {
    asm volatile("ldmatrix.sync.aligned.m8n8.x2.shared.b16 {%0,%1}, [%2];"
                 : "=r"(r[0]), "=r"(r[1]) : "r"(addr));
}
__device__ __forceinline__ void imma(int* d, const uint32_t* a, const uint32_t* b) {
    asm volatile("mma.sync.aligned.m16n8k32.row.col.s32.s8.s8.s32 "
                 "{%0,%1,%2,%3}, {%4,%5,%6,%7}, {%8,%9}, {%0,%1,%2,%3};"
                 : "+r"(d[0]), "+r"(d[1]), "+r"(d[2]), "+r"(d[3])
                 : "r"(a[0]), "r"(a[1]), "r"(a[2]), "r"(a[3]), "r"(b[0]), "r"(b[1]));
}

// ---------------- int8 two-chunk conversion ----------------------------------
// row -> sx, X1, X2 with x ~= sx*(X1 + X2/128), |X1|<=127, |X2|<=64
__device__ __forceinline__ float block_max_abs(float v, float* red) {
    int tid = threadIdx.x;
#pragma unroll
    for (int o = 16; o; o >>= 1) v = fmaxf(v, __shfl_xor_sync(0xffffffffu, v, o));
    if ((tid & 31) == 0) red[tid >> 5] = v;
    __syncthreads();
    if (tid < 8) {
        float w = red[tid];
#pragma unroll
        for (int o = 4; o; o >>= 1) w = fmaxf(w, __shfl_xor_sync(0xffu, w, o));
        if (tid == 0) red[0] = w;
    }
    __syncthreads();
    return red[0];
}

__device__ __forceinline__ void quant_row(const float4 v, float inv, float sx,
                                          int8_t* q1p, int8_t* q2p) {
    float f[4] = {v.x, v.y, v.z, v.w};
    char q1[4], q2[4];
#pragma unroll
    for (int i = 0; i < 4; i++) {
        int a = __float2int_rn(f[i] * inv);
        a = max(-127, min(127, a));
        float r = f[i] - (float)a * sx;
        int b = __float2int_rn(r * inv * 128.0f);
        b = max(-127, min(127, b));
        q1[i] = (char)a; q2[i] = (char)b;
    }
    *(char4*)q1p = make_char4(q1[0], q1[1], q1[2], q1[3]);
    *(char4*)q2p = make_char4(q2[0], q2[1], q2[2], q2[3]);
}

__global__ void convert_x_kernel(const float* __restrict__ x) {
    __shared__ float red[8];
    int m = blockIdx.x, c = threadIdx.x * 4;
    float4 v = *(const float4*)(x + (size_t)m * H_DIM + c);
    float mx = fmaxf(fmaxf(fabsf(v.x), fabsf(v.y)), fmaxf(fabsf(v.z), fabsf(v.w)));
    mx = block_max_abs(mx, red);
    float sx  = (mx > 0.f) ? mx / 127.0f : 1.0f;
    float inv = (mx > 0.f) ? 127.0f / mx : 0.0f;
    if (threadIdx.x == 0) g_sxa[m] = sx;
    quant_row(v, inv, sx, g_xa8 + (size_t)m * K2B + c, g_xa8 + (size_t)m * K2B + 1024 + c);
}

__global__ void convert_w_kernel(const float* __restrict__ W, const float* __restrict__ b,
                                 const int* __restrict__ omap) {
    __shared__ float red[8];
    int n = blockIdx.x, c = threadIdx.x * 4;
    int row = (n < V_OUT) ? omap[n] : -1;
    float4 v = make_float4(0.f, 0.f, 0.f, 0.f);
    if (row >= 0) v = *(const float4*)(W + (size_t)row * H_DIM + c);
    float mx = fmaxf(fmaxf(fabsf(v.x), fabsf(v.y)), fmaxf(fabsf(v.z), fabsf(v.w)));
    mx = block_max_abs(mx, red);
    float sx  = (mx > 0.f) ? mx / 127.0f : 1.0f;
    float inv = (mx > 0.f) ? 127.0f / mx : 0.0f;
    if (threadIdx.x == 0) {
        g_swb[n]   = sx;
        g_biasg[n] = (row >= 0) ? b[row] : 0.0f;
    }
    quant_row(v, inv, sx, g_wb8 + (size_t)n * K2B + c, g_wb8 + (size_t)n * K2B + 1024 + c);
}

// ---------------- scatter preprocessing --------------------------------------
__global__ void init_winner_kernel() {
    int i = blockIdx.x * blockDim.x + threadIdx.x;
    if (i < V_OUT) g_winner[i] = -1;
}
__global__ void max_winner_kernel(const int* __restrict__ i2a) {
    int i = blockIdx.x * blockDim.x + threadIdx.x;
    if (i < V_INP) atomicMax(&g_winner[i2a[i]], i);
}
__global__ void make_dest_kernel(const int* __restrict__ i2a) {
    int c = blockIdx.x * blockDim.x + threadIdx.x;
    if (c < V_INP) { int p = i2a[c]; g_dest[c] = (g_winner[p] == c) ? p : -1; }
}

// ---------------- IMMA GEMM ---------------------------------------------------
// Per k-group g, one 64KB stage holds {X1,X2,Y1,Y2}; three exact s32 terms:
//   S11 += X1*Y1 (acc1),  Scross += X1*Y2 + X2*Y1 (acc2)
// out = sx*sw*(S11 + Scross/128) + bias
__global__ __launch_bounds__(GTHR, 1)
void gemm_mma_kernel(const int* __restrict__ amask, float* __restrict__ gmask) {
    extern __shared__ char dyn[];
    __shared__ float bias_s[BNi], sw_s[BNi], sx_s[BMi];
    const uint32_t sb = smem_u32(dyn);
    const int tid  = threadIdx.x;
    const int lane = tid & 31;
    const int warp = tid >> 5;           // 0..7
    const int warpM = warp & 1;          // 2 warps in M (64 rows each)
    const int warpN = warp >> 1;         // 4 warps in N (32 cols each)
    const int mtile = blockIdx.x;        // 8 (fastest -> B-tile L2 reuse)
    const int ntile = blockIdx.y;        // 392

    if (tid < BNi) {
        bias_s[tid] = g_biasg[ntile * BNi + tid];
        sw_s[tid]   = g_swb[ntile * BNi + tid];
    }
    if (tid < BMi) sx_s[tid] = g_sxa[mtile * BMi + tid];

    int acc1[4][4][4], acc2[4][4][4];
#pragma unroll
    for (int mi = 0; mi < 4; mi++)
#pragma unroll
        for (int ni = 0; ni < 4; ni++)
#pragma unroll
            for (int q = 0; q < 4; q++) { acc1[mi][ni][q] = 0; acc2[mi][ni][q] = 0; }

    const uint32_t sw   = (uint32_t)((lane & 7) << 4);
    const uint32_t a_hi = (uint32_t)((lane >> 4) << 4);               // x4: lanes>=16 -> +16B
    const uint32_t b_hi = (uint32_t)((((lane & 15) >> 3) & 1) << 4);  // x2: lanes 8-15 -> +16B
    uint32_t a_row[4], b_row[4];
#pragma unroll
    for (int mi = 0; mi < 4; mi++)
        a_row[mi] = (uint32_t)((warpM * 64 + mi * 16 + (lane & 15)) * 128);
#pragma unroll
    for (int ni = 0; ni < 4; ni++)
        b_row[ni] = (uint32_t)((warpN * 32 + ni * 8 + (lane & 7)) * 128);

    const int8_t* abase = g_xa8 + (size_t)(mtile * BMi) * K2B;
    const int8_t* bbase = g_wb8 + (size_t)(ntile * BNi) * K2B;

    auto load_stage = [&](int g, int st) {
        const uint32_t stb = sb + st * STG;
        const int k0 = g * 128;
#pragma unroll
        for (int i = 0; i < 4; i++) {     // X1: 128 rows x 128B
            int q = i * GTHR + tid, row = q >> 3, c16 = q & 7;
            uint32_t so = SWZ((uint32_t)(row * 128 + c16 * 16));
            CP16(stb + X1OFF + so, abase + (size_t)row * K2B + k0 + c16 * 16);
            CP16(stb + X2OFF + so, abase + (size_t)row * K2B + 1024 + k0 + c16 * 16);
            CP16(stb + Y1OFF + so, bbase + (size_t)row * K2B + k0 + c16 * 16);
            CP16(stb + Y2OFF + so, bbase + (size_t)row * K2B + 1024 + k0 + c16 * 16);
        }
        CP_COMMIT();
    };

    load_stage(0, 0);
    load_stage(1, 1);

    for (int g = 0; g < NG; ++g) {
        if (g < NG - 1) CP_WAIT(1); else CP_WAIT(0);
        __syncthreads();
        if (g + 2 < NG) load_stage(g + 2, (g + 2) % STAGES);

        const uint32_t stb = sb + (g % STAGES) * STG;
#pragma unroll
        for (int ks = 0; ks < 4; ++ks) {
            const uint32_t kb  = (uint32_t)(ks * 32);
            const uint32_t ao  = (kb + a_hi) ^ sw;
            const uint32_t bo  = (kb + b_hi) ^ sw;
            uint32_t a1[4][4], b1[4][2], b2[4][2];
#pragma unroll
            for (int mi = 0; mi < 4; mi++) ldsm_x4(a1[mi], stb + X1OFF + a_row[mi] + ao);
#pragma unroll
            for (int ni = 0; ni < 4; ni++) ldsm_x2(b1[ni], stb + Y1OFF + b_row[ni] + bo);
#pragma unroll
            for (int ni = 0; ni < 4; ni++) ldsm_x2(b2[ni], stb + Y2OFF + b_row[ni] + bo);
#pragma unroll
            for (int mi = 0; mi < 4; mi++)
#pragma unroll
                for (int ni = 0; ni < 4; ni++) imma(acc1[mi][ni], a1[mi], b1[ni]);
#pragma unroll
            for (int mi = 0; mi < 4; mi++)
#pragma unroll
                for (int ni = 0; ni < 4; ni++) imma(acc2[mi][ni], a1[mi], b2[ni]);
            uint32_t a2[4][4];
#pragma unroll
            for (int mi = 0; mi < 4; mi++) ldsm_x4(a2[mi], stb + X2OFF + a_row[mi] + ao);
#pragma unroll
            for (int mi = 0; mi < 4; mi++)
#pragma unroll
                for (int ni = 0; ni < 4; ni++) imma(acc2[mi][ni], a2[mi], b1[ni]);
        }
    }
    __syncthreads();

    // ---- epilogue ----
    const int r  = lane >> 2;
    const int cp = (lane & 3) * 2;
#pragma unroll
    for (int mi = 0; mi < 4; mi++) {
#pragma unroll
        for (int ni = 0; ni < 4; ni++) {
            const int nl = warpN * 32 + ni * 8 + cp;
            const int n  = ntile * BNi + nl;
            if (n >= V_OUT) continue;
            const float sw0 = sw_s[nl], sw1 = sw_s[nl + 1];
            const float b0 = bias_s[nl], b1 = bias_s[nl + 1];
#pragma unroll
            for (int h = 0; h < 2; h++) {
                const int ml = warpM * 64 + mi * 16 + r + h * 8;
                const int m  = mtile * BMi + ml;
                const float sx = sx_s[ml];
                const size_t idx = (size_t)m * V_OUT + n;
                float s0 = (float)acc1[mi][ni][h * 2 + 0] + (float)acc2[mi][ni][h * 2 + 0] * 0.0078125f;
                float s1 = (float)acc1[mi][ni][h * 2 + 1] + (float)acc2[mi][ni][h * 2 + 1] * 0.0078125f;
                float2 gv;
                gv.x = sx * sw0 * s0 + b0;
                gv.y = sx * sw1 * s1 + b1;
                int2 mv = *(const int2*)(amask + idx);
                float2 gm;
                gm.x = gv.x - 1000000.0f * (float)mv.x;
                gm.y = gv.y - 1000000.0f * (float)mv.y;
                *(float2*)(g_scores + idx) = gv;
                *(float2*)(gmask + idx)    = gm;
            }
        }
    }
}

// ---------------- pointer scatter ---------------------------------------------
__global__ void scatter_kernel(const float* __restrict__ attn, const int* __restrict__ ctx) {
    int b = blockIdx.x, s = threadIdx.x;
    int c = ctx[b * SRC + s];
    int d = g_dest[c];
    if (d >= 0) atomicAdd(&g_scores[(size_t)b * V_OUT + d], attn[b * SRC + s]);
}

// ---------------- softmax: 2 passes (online max+sum, then write) --------------
__device__ __forceinline__ void ms_merge(float& m, float& s, float m2, float s2) {
    float nm = fmaxf(m, m2);
    s = s * __expf(m - nm) + s2 * __expf(m2 - nm);
    m = nm;
}

__global__ void softmax_kernel(float* __restrict__ probs) {
    __shared__ float redm[32], reds[32];
    const int b = blockIdx.x, tid = threadIdx.x;
    const float4* row4 = (const float4*)(g_scores + (size_t)b * V_OUT);
    const int NV4 = V_OUT / 4;

    float m = -3.4e38f, s = 0.0f;
    for (int i = tid; i < NV4; i += 1024) {
        float4 v = row4[i];
        float lm = fmaxf(fmaxf(v.x, v.y), fmaxf(v.z, v.w));
        float ls = __expf(v.x - lm) + __expf(v.y - lm)
                 + __expf(v.z - lm) + __expf(v.w - lm);
        ms_merge(m, s, lm, ls);
    }
#pragma unroll
    for (int o = 16; o; o >>= 1) {
        float m2 = __shfl_xor_sync(0xffffffffu, m, o);
        float s2 = __shfl_xor_sync(0xffffffffu, s, o);
        ms_merge(m, s, m2, s2);
    }
    if ((tid & 31) == 0) { redm[tid >> 5] = m; reds[tid >> 5] = s; }
    __syncthreads();
    if (tid < 32) {
        float mm = redm[tid], ss = reds[tid];
#pragma unroll
        for (int o = 16; o; o >>= 1) {
            float m2 = __shfl_xor_sync(0xffffffffu, mm, o);
            float s2 = __shfl_xor_sync(0xffffffffu, ss, o);
            ms_merge(mm, ss, m2, s2);
        }
        if (tid == 0) { redm[0] = mm; reds[0] = ss; }
    }
    __syncthreads();
    const float rmax = redm[0];
    const float inv  = 1.0f / reds[0];

    float4* out4 = (float4*)(probs + (size_t)b * V_OUT);
    for (int i = tid; i < NV4; i += 1024) {
        float4 v = row4[i];
        v.x = __expf(v.x - rmax) * inv;
        v.y = __expf(v.y - rmax) * inv;
        v.z = __expf(v.z - rmax) * inv;
        v.w = __expf(v.w - rmax) * inv;
        out4[i] = v;
    }
}

// ------------------------------------------------------------------------------
extern "C" void kernel_launch(void* const* d_in, const int* in_sizes, int n_in,
                              void* d_out, int out_size) {
    const float* x    = (const float*)d_in[0];
    const float* W    = (const float*)d_in[1];
    const float* bias = (const float*)d_in[2];
    const float* attn = (const float*)d_in[3];
    const int*   ctx  = (const int*)d_in[4];
    const int*   i2a  = (const int*)d_in[5];
    const int*   omap = (const int*)d_in[6];
    const int*   amsk = (const int*)d_in[7];

    float* probs = (float*)d_out;
    float* gmask = (float*)d_out + (size_t)B_DIM * V_OUT;

    static int smem_set = 0;
    if (!smem_set) {
        cudaFuncSetAttribute(gemm_mma_kernel, cudaFuncAttributeMaxDynamicSharedMemorySize,
                             STAGES * STG);
        smem_set = 1;
    }

    // GEMM stays in the ncu-captured slot (#4).
    convert_x_kernel<<<B_DIM, 256>>>(x);
    convert_w_kernel<<<NPAD, 256>>>(W, bias, omap);
    init_winner_kernel<<<(V_OUT + 255) / 256, 256>>>();

    dim3 grid(B_DIM / BMi, NPAD / BNi);   // (8, 392)
    gemm_mma_kernel<<<grid, GTHR, STAGES * STG>>>(amsk, gmask);

    max_winner_kernel<<<(V_INP + 255) / 256, 256>>>(i2a);
    make_dest_kernel<<<(V_INP + 255) / 256, 256>>>(i2a);
    scatter_kernel<<<B_DIM, SRC>>>(attn, ctx);
    softmax_kernel<<<B_DIM, 1024>>>(probs);
}

// round 8
// speedup vs baseline: 3.3064x; 3.3064x over previous
#include <cuda_runtime.h>
#include <cuda_fp16.h>
#include <cstdint>
#include <math.h>

#define B_DIM 1024
#define H_DIM 1024
#define KA    2048           // A' = [x_hi | x_lo] fp16
#define V_OUT 50000
#define V_INP 32000
#define SRC   256
#define NPAD  50176          // 392 * 128
#define BM    256
#define BN    128
#define NG    16             // k-groups of 64 fp16
#define B_SOFF  0
#define AH_OFF  16384
#define AL_OFF  49152
#define STG     81920        // B 16K + Ahi 32K + Alo 32K
#define NSTG    2
#define GTHR    256

// ---------------- scratch (device globals; no runtime alloc) ----------------
__device__ float  g_scores[(size_t)B_DIM * V_OUT];
__device__ __half g_xa[(size_t)B_DIM * KA];        // [x_hi | x_lo]
__device__ __half g_wh[(size_t)NPAD * H_DIM];      // gathered w, fp16
__device__ float  g_biasg[NPAD];
__device__ int    g_winner[V_OUT];
__device__ int    g_dest[V_INP];

// ---------------- PTX helpers -----------------------------------------------
__device__ __forceinline__ uint32_t smem_u32(const void* p) {
    uint32_t a;
    asm("{ .reg .u64 t; cvta.to.shared.u64 t, %1; cvt.u32.u64 %0, t; }" : "=r"(a) : "l"(p));
    return a;
}
#define CP16(dst, src)  asm volatile("cp.async.cg.shared.global [%0], [%1], 16;" :: "r"(dst), "l"(src))
#define CP_COMMIT()     asm volatile("cp.async.commit_group;" ::: "memory")
#define CP_WAIT(n)      asm volatile("cp.async.wait_group %0;" :: "n"(n) : "memory")
#define SWZ(b) ((b) ^ (((b) >> 3) & 0x70))

__device__ __forceinline__ void ldsm_x4(uint32_t* r, uint32_t addr) {
    asm volatile("ldmatrix.sync.aligned.m8n8.x4.shared.b16 {%0,%1,%2,%3}, [%4];"
                 : "=r"(r[0]), "=r"(r[1]), "=r"(r[2]), "=r"(r[3]) : "r"(addr));
}
__device__ __forceinline__ void mma16816(float* d, const uint32_t* a, const uint32_t* b) {
    asm volatile("mma.sync.aligned.m16n8k16.row.col.f32.f16.f16.f32 "
                 "{%0,%1,%2,%3}, {%4,%5,%6,%7}, {%8,%9}, {%0,%1,%2,%3};"
                 : "+f"(d[0]), "+f"(d[1]), "+f"(d[2]), "+f"(d[3])
                 : "r"(a[0]), "r"(a[1]), "r"(a[2]), "r"(a[3]), "r"(b[0]), "r"(b[1]));
}

// ---------------- conversion kernels ----------------------------------------
__global__ void convert_x_kernel(const float* __restrict__ x) {
    int m = blockIdx.x, c = threadIdx.x * 4;
    float4 v = *(const float4*)(x + (size_t)m * H_DIM + c);
    __half hx = __float2half_rn(v.x), hy = __float2half_rn(v.y);
    __half hz = __float2half_rn(v.z), hw = __float2half_rn(v.w);
    __half lx = __float2half_rn(v.x - __half2float(hx));
    __half ly = __float2half_rn(v.y - __half2float(hy));
    __half lz = __float2half_rn(v.z - __half2float(hz));
    __half lw = __float2half_rn(v.w - __half2float(hw));
    __half2 h0 = __halves2half2(hx, hy), h1 = __halves2half2(hz, hw);
    __half2 l0 = __halves2half2(lx, ly), l1 = __halves2half2(lz, lw);
    size_t base = (size_t)m * KA + c;
    uint2 uh, ul;
    uh.x = *(uint32_t*)&h0; uh.y = *(uint32_t*)&h1;
    ul.x = *(uint32_t*)&l0; ul.y = *(uint32_t*)&l1;
    *(uint2*)(g_xa + base)          = uh;
    *(uint2*)(g_xa + base + H_DIM)  = ul;
}

__global__ void convert_w_kernel(const float* __restrict__ W, const float* __restrict__ b,
                                 const int* __restrict__ omap) {
    int n = blockIdx.x, c = threadIdx.x * 4;
    int row = (n < V_OUT) ? omap[n] : -1;
    if (threadIdx.x == 0) g_biasg[n] = (row >= 0) ? b[row] : 0.0f;
    float4 v = make_float4(0.f, 0.f, 0.f, 0.f);
    if (row >= 0) v = *(const float4*)(W + (size_t)row * H_DIM + c);
    __half2 h0 = __floats2half2_rn(v.x, v.y);
    __half2 h1 = __floats2half2_rn(v.z, v.w);
    uint2 u; u.x = *(uint32_t*)&h0; u.y = *(uint32_t*)&h1;
    *(uint2*)(g_wh + (size_t)n * H_DIM + c) = u;
}

// ---------------- scatter preprocessing -------------------------------------
__global__ void init_winner_kernel() {
    int i = blockIdx.x * blockDim.x + threadIdx.x;
    if (i < V_OUT) g_winner[i] = -1;
}
__global__ void max_winner_kernel(const int* __restrict__ i2a) {
    int i = blockIdx.x * blockDim.x + threadIdx.x;
    if (i < V_INP) atomicMax(&g_winner[i2a[i]], i);
}
__global__ void make_dest_kernel(const int* __restrict__ i2a) {
    int c = blockIdx.x * blockDim.x + threadIdx.x;
    if (c < V_INP) { int p = i2a[c]; g_dest[c] = (g_winner[p] == c) ? p : -1; }
}

// ---------------- HMMA GEMM (fp16, 2-term A split, shared B) -----------------
// Per k-group g (64 fp16): acc += Ahi_g * B_g ; acc += Alo_g * B_g
// 256 threads, 8 warps, warp tile 64x64 (warpM=warp&3, warpN=warp>>2).
__global__ __launch_bounds__(GTHR, 1)
void gemm_mma_kernel(const int* __restrict__ amask, float* __restrict__ gmask) {
    extern __shared__ char dyn[];
    __shared__ float bias_s[BN];
    const uint32_t sb = smem_u32(dyn);
    const int tid  = threadIdx.x;
    const int lane = tid & 31;
    const int warp = tid >> 5;           // 0..7
    const int warpM = warp & 3;          // 4 warps in M (64 rows each)
    const int warpN = warp >> 2;         // 2 warps in N (64 cols each)
    const int mtile = blockIdx.x;        // 4 (fastest -> B-tile L2 reuse)
    const int ntile = blockIdx.y;        // 392

    if (tid < BN) bias_s[tid] = g_biasg[ntile * BN + tid];

    float acc[4][8][4];
#pragma unroll
    for (int mi = 0; mi < 4; mi++)
#pragma unroll
        for (int ni = 0; ni < 8; ni++)
#pragma unroll
            for (int q = 0; q < 4; q++) acc[mi][ni][q] = 0.0f;

    const uint32_t sw   = (uint32_t)((lane & 7) << 4);
    const uint32_t a_k2 = (uint32_t)((lane >> 4) << 4);        // A x4: lanes>=16 -> +16B (k hi)
    const uint32_t b_k2 = (uint32_t)(((lane >> 3) & 1) << 4);  // B pair-x4 k-half select
    uint32_t a_row[4], b_pair[4];
#pragma unroll
    for (int mi = 0; mi < 4; mi++)
        a_row[mi] = (uint32_t)((warpM * 64 + mi * 16 + (lane & 15)) * 128);
#pragma unroll
    for (int np = 0; np < 4; np++) {
        int row = warpN * 64 + np * 16 + ((lane >> 4) << 3) + (lane & 7);
        b_pair[np] = (uint32_t)(B_SOFF + row * 128);
    }

    const __half* abase = g_xa + (size_t)(mtile * BM) * KA;
    const __half* bbase = g_wh + (size_t)(ntile * BN) * H_DIM;

    auto load_stage = [&](int g, int st) {
        const uint32_t stb = sb + st * STG;
        const int k0 = g * 64;
#pragma unroll
        for (int i = 0; i < 4; i++) {     // B: 128 rows x 8 chunks = 1024 cp / 256 thr
            int q = i * GTHR + tid, row = q >> 3, c16 = q & 7;
            uint32_t so = SWZ((uint32_t)(row * 128 + c16 * 16));
            CP16(stb + B_SOFF + so, bbase + (size_t)row * H_DIM + k0 + c16 * 8);
        }
#pragma unroll
        for (int i = 0; i < 8; i++) {     // Ahi: 256 rows x 8 chunks = 2048 cp
            int q = i * GTHR + tid, row = q >> 3, c16 = q & 7;
            uint32_t so = SWZ((uint32_t)(row * 128 + c16 * 16));
            CP16(stb + AH_OFF + so, abase + (size_t)row * KA + k0 + c16 * 8);
        }
#pragma unroll
        for (int i = 0; i < 8; i++) {     // Alo
            int q = i * GTHR + tid, row = q >> 3, c16 = q & 7;
            uint32_t so = SWZ((uint32_t)(row * 128 + c16 * 16));
            CP16(stb + AL_OFF + so, abase + (size_t)row * KA + H_DIM + k0 + c16 * 8);
        }
        CP_COMMIT();
    };

    load_stage(0, 0);

    for (int g = 0; g < NG; ++g) {
        CP_WAIT(0);
        __syncthreads();                  // all warps past buf[(g+1)&1] use -> safe to refill
        if (g + 1 < NG) load_stage(g + 1, (g + 1) & 1);

        const uint32_t stb = sb + (g & 1) * STG;
#pragma unroll
        for (int ks = 0; ks < 4; ++ks) {
            const uint32_t kb = (uint32_t)(ks * 32);
            uint32_t bf[8][2], af[4][4];
            // B fragments: 4 paired-x4 loads -> 8 ni frags (shared by both A terms)
#pragma unroll
            for (int np = 0; np < 4; np++) {
                uint32_t r[4];
                ldsm_x4(r, stb + b_pair[np] + ((kb + b_k2) ^ sw));
                bf[np * 2 + 0][0] = r[0]; bf[np * 2 + 0][1] = r[1];
                bf[np * 2 + 1][0] = r[2]; bf[np * 2 + 1][1] = r[3];
            }
            // term 1: A_hi
#pragma unroll
            for (int mi = 0; mi < 4; mi++)
                ldsm_x4(af[mi], stb + AH_OFF + a_row[mi] + ((kb + a_k2) ^ sw));
#pragma unroll
            for (int mi = 0; mi < 4; mi++)
#pragma unroll
                for (int ni = 0; ni < 8; ni++)
                    mma16816(acc[mi][ni], af[mi], bf[ni]);
            // term 2: A_lo (same B frags)
#pragma unroll
            for (int mi = 0; mi < 4; mi++)
                ldsm_x4(af[mi], stb + AL_OFF + a_row[mi] + ((kb + a_k2) ^ sw));
#pragma unroll
            for (int mi = 0; mi < 4; mi++)
#pragma unroll
                for (int ni = 0; ni < 8; ni++)
                    mma16816(acc[mi][ni], af[mi], bf[ni]);
        }
    }
    __syncthreads();

    // ---- epilogue: +bias -> g_scores ; mask -> gmask ----
    const int r  = lane >> 2;
    const int cp = (lane & 3) * 2;
#pragma unroll
    for (int mi = 0; mi < 4; mi++) {
        const int m0 = mtile * BM + warpM * 64 + mi * 16 + r;
#pragma unroll
        for (int ni = 0; ni < 8; ni++) {
            const int nl = warpN * 64 + ni * 8 + cp;
            const int n  = ntile * BN + nl;
            if (n >= V_OUT) continue;
            const float b0 = bias_s[nl];
            const float b1 = bias_s[nl + 1];
#pragma unroll
            for (int h = 0; h < 2; h++) {
                const int m = m0 + h * 8;
                const size_t idx = (size_t)m * V_OUT + n;
                float2 g;
                g.x = acc[mi][ni][h * 2 + 0] + b0;
                g.y = acc[mi][ni][h * 2 + 1] + b1;
                int2 mv = *(const int2*)(amask + idx);
                float2 gm;
                gm.x = g.x - 1000000.0f * (float)mv.x;
                gm.y = g.y - 1000000.0f * (float)mv.y;
                *(float2*)(g_scores + idx) = g;
                *(float2*)(gmask + idx)    = gm;
            }
        }
    }
}

// ---------------- pointer scatter --------------------------------------------
__global__ void scatter_kernel(const float* __restrict__ attn, const int* __restrict__ ctx) {
    int b = blockIdx.x, s = threadIdx.x;
    int c = ctx[b * SRC + s];
    int d = g_dest[c];
    if (d >= 0) atomicAdd(&g_scores[(size_t)b * V_OUT + d], attn[b * SRC + s]);
}

// ---------------- softmax: 2 passes (online max+sum, then write) -------------
__device__ __forceinline__ void ms_merge(float& m, float& s, float m2, float s2) {
    float nm = fmaxf(m, m2);
    s = s * __expf(m - nm) + s2 * __expf(m2 - nm);
    m = nm;
}

__global__ void softmax_kernel(float* __restrict__ probs) {
    __shared__ float redm[32], reds[32];
    const int b = blockIdx.x, tid = threadIdx.x;
    const float4* row4 = (const float4*)(g_scores + (size_t)b * V_OUT);
    const int NV4 = V_OUT / 4;

    float m = -3.4e38f, s = 0.0f;
    for (int i = tid; i < NV4; i += 1024) {
        float4 v = row4[i];
        float lm = fmaxf(fmaxf(v.x, v.y), fmaxf(v.z, v.w));
        float ls = __expf(v.x - lm) + __expf(v.y - lm)
                 + __expf(v.z - lm) + __expf(v.w - lm);
        ms_merge(m, s, lm, ls);
    }
#pragma unroll
    for (int o = 16; o; o >>= 1) {
        float m2 = __shfl_xor_sync(0xffffffffu, m, o);
        float s2 = __shfl_xor_sync(0xffffffffu, s, o);
        ms_merge(m, s, m2, s2);
    }
    if ((tid & 31) == 0) { redm[tid >> 5] = m; reds[tid >> 5] = s; }
    __syncthreads();
    if (tid < 32) {
        float mm = redm[tid], ss = reds[tid];
#pragma unroll
        for (int o = 16; o; o >>= 1) {
            float m2 = __shfl_xor_sync(0xffffffffu, mm, o);
            float s2 = __shfl_xor_sync(0xffffffffu, ss, o);
            ms_merge(mm, ss, m2, s2);
        }
        if (tid == 0) { redm[0] = mm; reds[0] = ss; }
    }
    __syncthreads();
    const float rmax = redm[0];
    const float inv  = 1.0f / reds[0];

    float4* out4 = (float4*)(probs + (size_t)b * V_OUT);
    for (int i = tid; i < NV4; i += 1024) {
        float4 v = row4[i];
        v.x = __expf(v.x - rmax) * inv;
        v.y = __expf(v.y - rmax) * inv;
        v.z = __expf(v.z - rmax) * inv;
        v.w = __expf(v.w - rmax) * inv;
        out4[i] = v;
    }
}

// -----------------------------------------------------------------------------
extern "C" void kernel_launch(void* const* d_in, const int* in_sizes, int n_in,
                              void* d_out, int out_size) {
    const float* x    = (const float*)d_in[0];
    const float* W    = (const float*)d_in[1];
    const float* bias = (const float*)d_in[2];
    const float* attn = (const float*)d_in[3];
    const int*   ctx  = (const int*)d_in[4];
    const int*   i2a  = (const int*)d_in[5];
    const int*   omap = (const int*)d_in[6];
    const int*   amsk = (const int*)d_in[7];

    float* probs = (float*)d_out;
    float* gmask = (float*)d_out + (size_t)B_DIM * V_OUT;

    static int smem_set = 0;
    if (!smem_set) {
        cudaFuncSetAttribute(gemm_mma_kernel, cudaFuncAttributeMaxDynamicSharedMemorySize,
                             NSTG * STG);
        smem_set = 1;
    }

    // GEMM stays in the ncu-captured slot (#4).
    convert_x_kernel<<<B_DIM, 256>>>(x);
    convert_w_kernel<<<NPAD, 256>>>(W, bias, omap);
    init_winner_kernel<<<(V_OUT + 255) / 256, 256>>>();

    dim3 grid(B_DIM / BM, NPAD / BN);   // (4, 392)
    gemm_mma_kernel<<<grid, GTHR, NSTG * STG>>>(amsk, gmask);

    max_winner_kernel<<<(V_INP + 255) / 256, 256>>>(i2a);
    make_dest_kernel<<<(V_INP + 255) / 256, 256>>>(i2a);
    scatter_kernel<<<B_DIM, SRC>>>(attn, ctx);
    softmax_kernel<<<B_DIM, 1024>>>(probs);
}

// round 16
// speedup vs baseline: 3.3071x; 1.0002x over previous
#include <cuda_runtime.h>
#include <cuda_fp16.h>
#include <cstdint>
#include <math.h>

#define B_DIM 1024
#define H_DIM 1024
#define KA    2048           // A' = [x_hi | x_lo] fp16
#define V_OUT 50000
#define V_INP 32000
#define SRC   256
#define NPAD  50176          // 196 * 256
#define BM    128
#define BN    256
#define NG    16             // k-groups of 64 fp16
#define AH_OFF  0
#define AL_OFF  16384
#define B_SOFF  32768
#define STG     65536        // Ahi 16K + Alo 16K + B 32K
#define NSTG    3
#define GTHR    256
#define SMEM_SOFT (V_OUT * 4)   // 200000 B row cache for softmax

// ---------------- scratch (device globals; no runtime alloc) ----------------
__device__ float  g_scores[(size_t)B_DIM * V_OUT];
__device__ __half g_xa[(size_t)B_DIM * KA];        // [x_hi | x_lo]
__device__ __half g_wh[(size_t)NPAD * H_DIM];      // gathered w, fp16
__device__ float  g_biasg[NPAD];
__device__ int    g_winner[V_OUT];
__device__ int    g_dest[V_INP];

// ---------------- PTX helpers -----------------------------------------------
__device__ __forceinline__ uint32_t smem_u32(const void* p) {
    uint32_t a;
    asm("{ .reg .u64 t; cvta.to.shared.u64 t, %1; cvt.u32.u64 %0, t; }" : "=r"(a) : "l"(p));
    return a;
}
#define CP16(dst, src)  asm volatile("cp.async.cg.shared.global [%0], [%1], 16;" :: "r"(dst), "l"(src))
#define CP_COMMIT()     asm volatile("cp.async.commit_group;" ::: "memory")
#define CP_WAIT(n)      asm volatile("cp.async.wait_group %0;" :: "n"(n) : "memory")
#define SWZ(b) ((b) ^ (((b) >> 3) & 0x70))

__device__ __forceinline__ void ldsm_x4(uint32_t* r, uint32_t addr) {
    asm volatile("ldmatrix.sync.aligned.m8n8.x4.shared.b16 {%0,%1,%2,%3}, [%4];"
                 : "=r"(r[0]), "=r"(r[1]), "=r"(r[2]), "=r"(r[3]) : "r"(addr));
}
__device__ __forceinline__ void mma16816(float* d, const uint32_t* a, const uint32_t* b) {
    asm volatile("mma.sync.aligned.m16n8k16.row.col.f32.f16.f16.f32 "
                 "{%0,%1,%2,%3}, {%4,%5,%6,%7}, {%8,%9}, {%0,%1,%2,%3};"
                 : "+f"(d[0]), "+f"(d[1]), "+f"(d[2]), "+f"(d[3])
                 : "r"(a[0]), "r"(a[1]), "r"(a[2]), "r"(a[3]), "r"(b[0]), "r"(b[1]));
}

// ---------------- conversion kernels ----------------------------------------
__global__ void convert_x_kernel(const float* __restrict__ x) {
    int m = blockIdx.x, c = threadIdx.x * 4;
    float4 v = *(const float4*)(x + (size_t)m * H_DIM + c);
    __half hx = __float2half_rn(v.x), hy = __float2half_rn(v.y);
    __half hz = __float2half_rn(v.z), hw = __float2half_rn(v.w);
    __half lx = __float2half_rn(v.x - __half2float(hx));
    __half ly = __float2half_rn(v.y - __half2float(hy));
    __half lz = __float2half_rn(v.z - __half2float(hz));
    __half lw = __float2half_rn(v.w - __half2float(hw));
    __half2 h0 = __halves2half2(hx, hy), h1 = __halves2half2(hz, hw);
    __half2 l0 = __halves2half2(lx, ly), l1 = __halves2half2(lz, lw);
    size_t base = (size_t)m * KA + c;
    uint2 uh, ul;
    uh.x = *(uint32_t*)&h0; uh.y = *(uint32_t*)&h1;
    ul.x = *(uint32_t*)&l0; ul.y = *(uint32_t*)&l1;
    *(uint2*)(g_xa + base)          = uh;
    *(uint2*)(g_xa + base + H_DIM)  = ul;
}

__global__ void convert_w_kernel(const float* __restrict__ W, const float* __restrict__ b,
                                 const int* __restrict__ omap) {
    int n = blockIdx.x, c = threadIdx.x * 4;
    int row = (n < V_OUT) ? omap[n] : -1;
    if (threadIdx.x == 0) g_biasg[n] = (row >= 0) ? b[row] : 0.0f;
    float4 v = make_float4(0.f, 0.f, 0.f, 0.f);
    if (row >= 0) v = *(const float4*)(W + (size_t)row * H_DIM + c);
    __half2 h0 = __floats2half2_rn(v.x, v.y);
    __half2 h1 = __floats2half2_rn(v.z, v.w);
    uint2 u; u.x = *(uint32_t*)&h0; u.y = *(uint32_t*)&h1;
    *(uint2*)(g_wh + (size_t)n * H_DIM + c) = u;
}

// ---------------- scatter preprocessing -------------------------------------
__global__ void init_winner_kernel() {
    int i = blockIdx.x * blockDim.x + threadIdx.x;
    if (i < V_OUT) g_winner[i] = -1;
}
__global__ void max_winner_kernel(const int* __restrict__ i2a) {
    int i = blockIdx.x * blockDim.x + threadIdx.x;
    if (i < V_INP) atomicMax(&g_winner[i2a[i]], i);
}
__global__ void make_dest_kernel(const int* __restrict__ i2a) {
    int c = blockIdx.x * blockDim.x + threadIdx.x;
    if (c < V_INP) { int p = i2a[c]; g_dest[c] = (g_winner[p] == c) ? p : -1; }
}

// ---------------- HMMA GEMM (fp16, 2-term A split, shared B) -----------------
// BM=128 x BN=256; per k-group g (64 fp16): acc += Ahi_g*B_g ; acc += Alo_g*B_g
// 256 threads, 8 warps, warp tile 64x64 (warpM=warp&1 -> 2 in M, warpN=warp>>1 -> 4 in N).
__global__ __launch_bounds__(GTHR, 1)
void gemm_mma_kernel(const int* __restrict__ amask, float* __restrict__ gmask) {
    extern __shared__ char dyn[];
    __shared__ float bias_s[BN];
    const uint32_t sb = smem_u32(dyn);
    const int tid  = threadIdx.x;
    const int lane = tid & 31;
    const int warp = tid >> 5;           // 0..7
    const int warpM = warp & 1;          // 2 warps in M (64 rows each)
    const int warpN = warp >> 1;         // 4 warps in N (64 cols each)
    const int mtile = blockIdx.x;        // 8 (fastest -> B-tile L2 reuse)
    const int ntile = blockIdx.y;        // 196

    bias_s[tid] = g_biasg[ntile * BN + tid];

    float acc[4][8][4];
#pragma unroll
    for (int mi = 0; mi < 4; mi++)
#pragma unroll
        for (int ni = 0; ni < 8; ni++)
#pragma unroll
            for (int q = 0; q < 4; q++) acc[mi][ni][q] = 0.0f;

    const uint32_t sw   = (uint32_t)((lane & 7) << 4);
    const uint32_t a_k2 = (uint32_t)((lane >> 4) << 4);        // A x4: lanes>=16 -> +16B (k hi)
    const uint32_t b_k2 = (uint32_t)(((lane >> 3) & 1) << 4);  // B pair-x4 k-half select
    uint32_t a_row[4], b_pair[4];
#pragma unroll
    for (int mi = 0; mi < 4; mi++)
        a_row[mi] = (uint32_t)((warpM * 64 + mi * 16 + (lane & 15)) * 128);
#pragma unroll
    for (int np = 0; np < 4; np++) {
        int row = warpN * 64 + np * 16 + ((lane >> 4) << 3) + (lane & 7);
        b_pair[np] = (uint32_t)(B_SOFF + row * 128);
    }

    const __half* abase = g_xa + (size_t)(mtile * BM) * KA;
    const __half* bbase = g_wh + (size_t)(ntile * BN) * H_DIM;

    auto load_stage = [&](int g, int st) {
        const uint32_t stb = sb + st * STG;
        const int k0 = g * 64;
#pragma unroll
        for (int i = 0; i < 4; i++) {     // Ahi: 128 rows x 8 chunks = 1024 cp / 256 thr
            int q = i * GTHR + tid, row = q >> 3, c16 = q & 7;
            uint32_t so = SWZ((uint32_t)(row * 128 + c16 * 16));
            CP16(stb + AH_OFF + so, abase + (size_t)row * KA + k0 + c16 * 8);
        }
#pragma unroll
        for (int i = 0; i < 4; i++) {     // Alo
            int q = i * GTHR + tid, row = q >> 3, c16 = q & 7;
            uint32_t so = SWZ((uint32_t)(row * 128 + c16 * 16));
            CP16(stb + AL_OFF + so, abase + (size_t)row * KA + H_DIM + k0 + c16 * 8);
        }
#pragma unroll
        for (int i = 0; i < 8; i++) {     // B: 256 rows x 8 chunks = 2048 cp
            int q = i * GTHR + tid, row = q >> 3, c16 = q & 7;
            uint32_t so = SWZ((uint32_t)(row * 128 + c16 * 16));
            CP16(stb + B_SOFF + so, bbase + (size_t)row * H_DIM + k0 + c16 * 8);
        }
        CP_COMMIT();
    };

    load_stage(0, 0);
    load_stage(1, 1);

    int st_c = 0, st_n = 2;   // stage of chunk g, stage for prefetch g+2
    for (int g = 0; g < NG; ++g) {
        if (g < NG - 1) CP_WAIT(1); else CP_WAIT(0);
        __syncthreads();                  // all warps done with stage st_n (used at g-1)
        if (g + 2 < NG) load_stage(g + 2, st_n);

        const uint32_t stb = sb + st_c * STG;
#pragma unroll
        for (int ks = 0; ks < 4; ++ks) {
            const uint32_t kb = (uint32_t)(ks * 32);
            uint32_t bf[8][2], af[4][4];
            // B fragments: 4 paired-x4 loads -> 8 ni frags (shared by both A terms)
#pragma unroll
            for (int np = 0; np < 4; np++) {
                uint32_t r[4];
                ldsm_x4(r, stb + b_pair[np] + ((kb + b_k2) ^ sw));
                bf[np * 2 + 0][0] = r[0]; bf[np * 2 + 0][1] = r[1];
                bf[np * 2 + 1][0] = r[2]; bf[np * 2 + 1][1] = r[3];
            }
            // term 1: A_hi
#pragma unroll
            for (int mi = 0; mi < 4; mi++)
                ldsm_x4(af[mi], stb + AH_OFF + a_row[mi] + ((kb + a_k2) ^ sw));
#pragma unroll
            for (int mi = 0; mi < 4; mi++)
#pragma unroll
                for (int ni = 0; ni < 8; ni++)
                    mma16816(acc[mi][ni], af[mi], bf[ni]);
            // term 2: A_lo (same B frags)
#pragma unroll
            for (int mi = 0; mi < 4; mi++)
                ldsm_x4(af[mi], stb + AL_OFF + a_row[mi] + ((kb + a_k2) ^ sw));
#pragma unroll
            for (int mi = 0; mi < 4; mi++)
#pragma unroll
                for (int ni = 0; ni < 8; ni++)
                    mma16816(acc[mi][ni], af[mi], bf[ni]);
        }
        st_c = (st_c + 1) % NSTG;
        st_n = (st_n + 1) % NSTG;
    }
    __syncthreads();

    // ---- epilogue: +bias -> g_scores ; mask -> gmask ----
    const int r  = lane >> 2;
    const int cp = (lane & 3) * 2;
#pragma unroll
    for (int mi = 0; mi < 4; mi++) {
        const int m0 = mtile * BM + warpM * 64 + mi * 16 + r;
#pragma unroll
        for (int ni = 0; ni < 8; ni++) {
            const int nl = warpN * 64 + ni * 8 + cp;
            const int n  = ntile * BN + nl;
            if (n >= V_OUT) continue;
            const float b0 = bias_s[nl];
            const float b1 = bias_s[nl + 1];
#pragma unroll
            for (int h = 0; h < 2; h++) {
                const int m = m0 + h * 8;
                const size_t idx = (size_t)m * V_OUT + n;
                float2 g;
                g.x = acc[mi][ni][h * 2 + 0] + b0;
                g.y = acc[mi][ni][h * 2 + 1] + b1;
                int2 mv = *(const int2*)(amask + idx);
                float2 gm;
                gm.x = g.x - 1000000.0f * (float)mv.x;
                gm.y = g.y - 1000000.0f * (float)mv.y;
                *(float2*)(g_scores + idx) = g;
                *(float2*)(gmask + idx)    = gm;
            }
        }
    }
}

// ---------------- pointer scatter --------------------------------------------
__global__ void scatter_kernel(const float* __restrict__ attn, const int* __restrict__ ctx) {
    int b = blockIdx.x, s = threadIdx.x;
    int c = ctx[b * SRC + s];
    int d = g_dest[c];
    if (d >= 0) atomicAdd(&g_scores[(size_t)b * V_OUT + d], attn[b * SRC + s]);
}

// ---------------- softmax: single DRAM read (row cached in smem) -------------
__device__ __forceinline__ void ms_merge(float& m, float& s, float m2, float s2) {
    float nm = fmaxf(m, m2);
    s = s * __expf(m - nm) + s2 * __expf(m2 - nm);
    m = nm;
}

__global__ void softmax_kernel(float* __restrict__ probs) {
    extern __shared__ float rowbuf[];          // V_OUT floats = 200 KB
    __shared__ float redm[32], reds[32];
    const int b = blockIdx.x, tid = threadIdx.x;
    const float4* row4 = (const float4*)(g_scores + (size_t)b * V_OUT);
    float4* buf4 = (float4*)rowbuf;
    const int NV4 = V_OUT / 4;                 // 12500

    // Pass 1: stream row from DRAM once -> smem; online (max, sum)
    float m = -3.4e38f, s = 0.0f;
    for (int i = tid; i < NV4; i += 1024) {
        float4 v = row4[i];
        buf4[i] = v;
        float lm = fmaxf(fmaxf(v.x, v.y), fmaxf(v.z, v.w));
        float ls = __expf(v.x - lm) + __expf(v.y - lm)
                 + __expf(v.z - lm) + __expf(v.w - lm);
        ms_merge(m, s, lm, ls);
    }
#pragma unroll
    for (int o = 16; o; o >>= 1) {
        float m2 = __shfl_xor_sync(0xffffffffu, m, o);
        float s2 = __shfl_xor_sync(0xffffffffu, s, o);
        ms_merge(m, s, m2, s2);
    }
    if ((tid & 31) == 0) { redm[tid >> 5] = m; reds[tid >> 5] = s; }
    __syncthreads();
    if (tid < 32) {
        float mm = redm[tid], ss = reds[tid];
#pragma unroll
        for (int o = 16; o; o >>= 1) {
            float m2 = __shfl_xor_sync(0xffffffffu, mm, o);
            float s2 = __shfl_xor_sync(0xffffffffu, ss, o);
            ms_merge(mm, ss, m2, s2);
        }
        if (tid == 0) { redm[0] = mm; reds[0] = ss; }
    }
    __syncthreads();
    const float rmax = redm[0];
    const float inv  = 1.0f / reds[0];

    // Pass 2: read from smem, write probs
    float4* out4 = (float4*)(probs + (size_t)b * V_OUT);
    for (int i = tid; i < NV4; i += 1024) {
        float4 v = buf4[i];
        v.x = __expf(v.x - rmax) * inv;
        v.y = __expf(v.y - rmax) * inv;
        v.z = __expf(v.z - rmax) * inv;
        v.w = __expf(v.w - rmax) * inv;
        out4[i] = v;
    }
}

// -----------------------------------------------------------------------------
extern "C" void kernel_launch(void* const* d_in, const int* in_sizes, int n_in,
                              void* d_out, int out_size) {
    const float* x    = (const float*)d_in[0];
    const float* W    = (const float*)d_in[1];
    const float* bias = (const float*)d_in[2];
    const float* attn = (const float*)d_in[3];
    const int*   ctx  = (const int*)d_in[4];
    const int*   i2a  = (const int*)d_in[5];
    const int*   omap = (const int*)d_in[6];
    const int*   amsk = (const int*)d_in[7];

    float* probs = (float*)d_out;
    float* gmask = (float*)d_out + (size_t)B_DIM * V_OUT;

    static int smem_set = 0;
    if (!smem_set) {
        cudaFuncSetAttribute(gemm_mma_kernel, cudaFuncAttributeMaxDynamicSharedMemorySize,
                             NSTG * STG);
        cudaFuncSetAttribute(softmax_kernel, cudaFuncAttributeMaxDynamicSharedMemorySize,
                             SMEM_SOFT);
        smem_set = 1;
    }

    // GEMM stays in the ncu-captured slot (#4).
    convert_x_kernel<<<B_DIM, 256>>>(x);
    convert_w_kernel<<<NPAD, 256>>>(W, bias, omap);
    init_winner_kernel<<<(V_OUT + 255) / 256, 256>>>();

    dim3 grid(B_DIM / BM, NPAD / BN);   // (8, 196)
    gemm_mma_kernel<<<grid, GTHR, NSTG * STG>>>(amsk, gmask);

    max_winner_kernel<<<(V_INP + 255) / 256, 256>>>(i2a);
    make_dest_kernel<<<(V_INP + 255) / 256, 256>>>(i2a);
    scatter_kernel<<<B_DIM, SRC>>>(attn, ctx);
    softmax_kernel<<<B_DIM, 1024, SMEM_SOFT>>>(probs);
}